// round 13
// baseline (speedup 1.0000x reference)
#include <cuda_runtime.h>
#include <cuda_bf16.h>
#include <cstdint>

// ---------------------------------------------------------------------------
// LJ 12-6 over a neighbor list. Round 13: WARP-SPECIALIZED producer-consumer.
//
// R12 proved decoupled filter/LJ beats fused (~42us vs ~48us) but serialized
// them and paid 12us of helper overhead. Now one kernel, 148 CTAs x 1024thr:
//   warps 0..23  (producers): cell-filter 256-pair chunks, ballot-compact
//     survivors into g_surv[c*256..], publish count via fence + volatile st.
//   warps 24..31 (consumers): spin (nanosleep) on g_cnt[c], fence, then dense
//     LJ on survivors with red.global.add.v4 into g_acc.
// Deadlock-free (producers never wait; 1 CTA/SM => all co-resident).
// g_surv read once, only after its flag, via __ldcg (L2) => no stale L1.
// prep zeroes g_acc and resets g_cnt; writeout is read-only, 1 atom/thread.
// ---------------------------------------------------------------------------

#define MAX_ATOMS  200000
#define MAX_CHUNKS 50048                  // >= ceil(12.8M/256)
#define CTAS       148
#define THR        1024
#define FILT_WARPS 24
#define LJ_WARPS   8

__device__ __align__(16) float4 g_acc[MAX_ATOMS];   // {E,fx,fy,fz}
__device__ float4 g_R4[MAX_ATOMS];
__device__ __align__(16) unsigned char g_cellid[MAX_ATOMS];
__device__ int2 g_surv[(long long)MAX_CHUNKS * 256];
__device__ int  g_cnt[MAX_CHUNKS];

// sel = ci - cj + 43 in [0,86]; bit set iff diff can arise from |dx|,|dy|,|dz|<=1
#define ADJ_LO ((7ULL<<0)|(7ULL<<6)|(7ULL<<12)|(7ULL<<36)|(7ULL<<42)|(7ULL<<48))
#define ADJ_HI ((7ULL<<8)|(7ULL<<14)|(7ULL<<20))

// Kernel A: pack positions, cell ids, zero accumulators, reset chunk flags.
__global__ void prep_kernel(const float* __restrict__ R, int n_atoms,
                            int nchunks) {
    int a = blockIdx.x * blockDim.x + threadIdx.x;
    if (a < n_atoms) {
        float x = __ldg(&R[3 * a + 0]);
        float y = __ldg(&R[3 * a + 1]);
        float z = __ldg(&R[3 * a + 2]);
        g_R4[a] = make_float4(x, y, z, 0.0f);
        const float s = 1.0f / 10.01f;          // cell width 10.01 > cutoff=10
        int cx = min((int)(x * s), 5);
        int cy = min((int)(y * s), 5);
        int cz = min((int)(z * s), 5);
        g_cellid[a] = (unsigned char)(cx * 36 + cy * 6 + cz);
        g_acc[a] = make_float4(0.0f, 0.0f, 0.0f, 0.0f);
    }
    if (a < nchunks) g_cnt[a] = -1;
}

// Kernel B: warp-specialized filter (producers) + LJ (consumers).
__global__ __launch_bounds__(THR, 1) void fused_pc_kernel(
        const int* __restrict__ idx_i,
        const int* __restrict__ idx_j,
        const float* __restrict__ p_eps,
        const float* __restrict__ p_sig,
        const float* __restrict__ p_cut,
        int n_atoms, int n_pairs, int nchunks) {
    extern __shared__ unsigned char s_cell[];

    // Cooperative table fill (coalesced int4) — all 32 warps.
    {
        int n16 = n_atoms >> 4;
        const int4* src = reinterpret_cast<const int4*>(g_cellid);
        int4* dst = reinterpret_cast<int4*>(s_cell);
        for (int k = threadIdx.x; k < n16; k += THR) dst[k] = src[k];
        for (int k = (n16 << 4) + threadIdx.x; k < n_atoms; k += THR)
            s_cell[k] = g_cellid[k];
    }
    __syncthreads();

    const int lane = threadIdx.x & 31;
    const int warp = threadIdx.x >> 5;

    if (warp < FILT_WARPS) {
        // ======================= PRODUCER: filter =======================
        const unsigned lt = (1u << lane) - 1u;
        const int fw  = blockIdx.x * FILT_WARPS + warp;
        const int nfw = gridDim.x * FILT_WARPS;

        for (int c = fw; c < nchunks; c += nfw) {
            const int base = c << 8;
            int2* __restrict__ obase = g_surv + ((long long)c << 8);
            int wcnt = 0;

            #pragma unroll
            for (int half = 0; half < 2; half++) {
                int p0 = base + (half << 7) + (lane << 2);
                int ii[4], jj[4];
                unsigned livemask;
                if (p0 + 3 < n_pairs) {
                    int q = p0 >> 2;
                    int4 vi = __ldg(reinterpret_cast<const int4*>(idx_i) + q);
                    int4 vj = __ldg(reinterpret_cast<const int4*>(idx_j) + q);
                    ii[0]=vi.x; ii[1]=vi.y; ii[2]=vi.z; ii[3]=vi.w;
                    jj[0]=vj.x; jj[1]=vj.y; jj[2]=vj.z; jj[3]=vj.w;
                    livemask = 0xfu;
                } else {
                    livemask = 0u;
                    #pragma unroll
                    for (int k = 0; k < 4; k++) {
                        int p = p0 + k;
                        bool lv = (p < n_pairs);
                        livemask |= (unsigned)lv << k;
                        ii[k] = lv ? __ldg(&idx_i[p]) : 0;
                        jj[k] = lv ? __ldg(&idx_j[p]) : 0;
                    }
                }

                int ca[4], cb[4];
                #pragma unroll
                for (int k = 0; k < 4; k++) ca[k] = s_cell[ii[k]];
                #pragma unroll
                for (int k = 0; k < 4; k++) cb[k] = s_cell[jj[k]];

                unsigned pass = 0;
                #pragma unroll
                for (int k = 0; k < 4; k++) {
                    unsigned sel = (unsigned)(ca[k] - cb[k] + 43);
                    unsigned long long m = (sel >= 64u) ? ADJ_HI : ADJ_LO;
                    unsigned bit = (unsigned)(m >> (sel & 63u)) & 1u;
                    bit &= (unsigned)(sel < 87u);
                    pass |= bit << k;
                }
                pass &= livemask;

                #pragma unroll
                for (int k = 0; k < 4; k++) {
                    unsigned m = __ballot_sync(0xffffffffu, (pass >> k) & 1u);
                    if ((pass >> k) & 1u) {
                        int off = wcnt + __popc(m & lt);
                        obase[off] = make_int2(ii[k], jj[k]);
                    }
                    wcnt += __popc(m);
                }
            }

            __syncwarp();
            __threadfence();                       // survivors visible first
            if (lane == 0)
                *reinterpret_cast<volatile int*>(&g_cnt[c]) = wcnt;
        }
    } else {
        // ======================= CONSUMER: LJ ===========================
        const float eps  = __ldg(p_eps);
        const float sig  = __ldg(p_sig);
        const float cut2 = __ldg(p_cut) * __ldg(p_cut);
        const float sig2 = sig * sig;

        const int lw  = blockIdx.x * LJ_WARPS + (warp - FILT_WARPS);
        const int nlw = gridDim.x * LJ_WARPS;

        for (int c = lw; c < nchunks; c += nlw) {
            int cnt;
            while ((cnt = *reinterpret_cast<volatile int*>(&g_cnt[c])) < 0)
                __nanosleep(64);
            __threadfence();                       // acquire: order loads

            const int2* __restrict__ sbase = g_surv + ((long long)c << 8);
            for (int r = lane; r < cnt; r += 32) {
                int2 pr = __ldcg(sbase + r);
                int i = pr.x, j = pr.y;
                float4 Ri = __ldg(&g_R4[i]);
                float4 Rj = __ldg(&g_R4[j]);
                float dx = Ri.x - Rj.x;
                float dy = Ri.y - Rj.y;
                float dz = Ri.z - Rj.z;
                float r2 = fmaf(dx, dx, fmaf(dy, dy, dz * dz));
                if (r2 < cut2 && r2 > 1e-10f) {
                    float inv  = __fdividef(1.0f, r2);
                    float sr2  = sig2 * inv;
                    float sr6  = sr2 * sr2 * sr2;
                    float sr12 = sr6 * sr6;
                    float e    = 2.0f * eps * (sr12 - sr6);  // 0.5*4eps folded
                    float fm   = 24.0f * eps * fmaf(2.0f, sr12, -sr6) * inv;
                    asm volatile("red.global.add.v4.f32 [%0], {%1, %2, %3, %4};"
                                 :: "l"(&g_acc[i]),
                                    "f"(e), "f"(fm*dx), "f"(fm*dy), "f"(fm*dz)
                                 : "memory");
                }
            }
        }
    }
}

// Kernel C: read-only reshape into output layout. 1 atom/thread.
__global__ void writeout_kernel(float* __restrict__ out, int n_atoms) {
    int a = blockIdx.x * blockDim.x + threadIdx.x;
    if (a < n_atoms) {
        float4 v = g_acc[a];
        out[a] = v.x;
        float* f = out + n_atoms;
        f[3 * a + 0] = v.y;
        f[3 * a + 1] = v.z;
        f[3 * a + 2] = v.w;
    }
}

extern "C" void kernel_launch(void* const* d_in, const int* in_sizes, int n_in,
                              void* d_out, int out_size) {
    const float* R     = (const float*)d_in[0];
    const float* eps   = (const float*)d_in[1];
    const float* sig   = (const float*)d_in[2];
    const float* cut   = (const float*)d_in[3];
    const int*   idx_i = (const int*)d_in[4];
    const int*   idx_j = (const int*)d_in[5];
    float*       out   = (float*)d_out;

    int n_atoms = in_sizes[0] / 3;
    int n_pairs = in_sizes[4];
    int nchunks = (n_pairs + 255) / 256;
    if (nchunks > MAX_CHUNKS) nchunks = MAX_CHUNKS;

    int smem_bytes = n_atoms;   // 1 byte per atom (200 KB)
    cudaFuncSetAttribute(fused_pc_kernel,
                         cudaFuncAttributeMaxDynamicSharedMemorySize, smem_bytes);

    int blocks_atoms = (n_atoms + 255) / 256;

    prep_kernel<<<blocks_atoms, 256>>>(R, n_atoms, nchunks);
    fused_pc_kernel<<<CTAS, THR, smem_bytes>>>(
        idx_i, idx_j, eps, sig, cut, n_atoms, n_pairs, nchunks);
    writeout_kernel<<<blocks_atoms, 256>>>(out, n_atoms);
}

// round 14
// speedup vs baseline: 1.7206x; 1.7206x over previous
#include <cuda_runtime.h>
#include <cuda_bf16.h>
#include <cstdint>

// ---------------------------------------------------------------------------
// LJ 12-6 over a neighbor list. Round 14: R12's decoupled filter+LJ (best
// measured dataflow: ~42us for the two hot kernels) with helper kernels
// slimmed to their measured-minimal shapes.
//   prep:     pack R, cell ids, zero g_acc, reset g_cnt   (~5.4us, measured)
//   filter:   warp-per-256-pair chunk, smem cell table, ballot compaction,
//             NO atomics (R12 verbatim)
//   lj:       dense survivors, high occupancy, red.global.add.v4 (R12 verbatim)
//   writeout: READ-ONLY reshape, 1 atom/thread (~3us)
// ---------------------------------------------------------------------------

#define MAX_ATOMS  200000
#define MAX_CHUNKS 50048                  // >= ceil(12.8M/256)
#define FILT_CTAS  148
#define FILT_THR   1024

__device__ __align__(16) float4 g_acc[MAX_ATOMS];   // {E,fx,fy,fz}
__device__ float4 g_R4[MAX_ATOMS];
__device__ __align__(16) unsigned char g_cellid[MAX_ATOMS];
__device__ int2 g_surv[(long long)MAX_CHUNKS * 256];
__device__ int  g_cnt[MAX_CHUNKS];

// sel = ci - cj + 43 in [0,86]; bit set iff diff can arise from |dx|,|dy|,|dz|<=1
#define ADJ_LO ((7ULL<<0)|(7ULL<<6)|(7ULL<<12)|(7ULL<<36)|(7ULL<<42)|(7ULL<<48))
#define ADJ_HI ((7ULL<<8)|(7ULL<<14)|(7ULL<<20))

// Kernel A: pack positions, cell ids, zero accumulators, reset chunk counts.
__global__ void prep_kernel(const float* __restrict__ R, int n_atoms,
                            int nchunks) {
    int a = blockIdx.x * blockDim.x + threadIdx.x;
    if (a < n_atoms) {
        float x = __ldg(&R[3 * a + 0]);
        float y = __ldg(&R[3 * a + 1]);
        float z = __ldg(&R[3 * a + 2]);
        g_R4[a] = make_float4(x, y, z, 0.0f);
        const float s = 1.0f / 10.01f;          // cell width 10.01 > cutoff=10
        int cx = min((int)(x * s), 5);
        int cy = min((int)(y * s), 5);
        int cz = min((int)(z * s), 5);
        g_cellid[a] = (unsigned char)(cx * 36 + cy * 6 + cz);
        g_acc[a] = make_float4(0.0f, 0.0f, 0.0f, 0.0f);
    }
    if (a < nchunks) g_cnt[a] = 0;
}

// Kernel B: filter. One warp per 256-pair chunk; no atomics anywhere.
__global__ __launch_bounds__(FILT_THR, 1) void filter_kernel(
        const int* __restrict__ idx_i,
        const int* __restrict__ idx_j,
        int n_atoms, int n_pairs, int nchunks) {
    extern __shared__ unsigned char s_cell[];

    // Cooperative table fill (coalesced int4).
    {
        int n16 = n_atoms >> 4;
        const int4* src = reinterpret_cast<const int4*>(g_cellid);
        int4* dst = reinterpret_cast<int4*>(s_cell);
        for (int k = threadIdx.x; k < n16; k += FILT_THR) dst[k] = src[k];
        for (int k = (n16 << 4) + threadIdx.x; k < n_atoms; k += FILT_THR)
            s_cell[k] = g_cellid[k];
    }
    __syncthreads();

    const int lane   = threadIdx.x & 31;
    const int gwarp  = (blockIdx.x * FILT_THR + threadIdx.x) >> 5;
    const int nwarps = gridDim.x * (FILT_THR >> 5);
    const unsigned lt = (1u << lane) - 1u;

    for (int c = gwarp; c < nchunks; c += nwarps) {
        const int base = c << 8;                  // first pair of this chunk
        int2* __restrict__ obase = g_surv + ((long long)c << 8);
        int wcnt = 0;                             // warp-uniform survivor count

        #pragma unroll
        for (int half = 0; half < 2; half++) {
            // 128 pairs: one int4 per lane.
            int p0 = base + (half << 7) + (lane << 2);
            int ii[4], jj[4];
            unsigned livemask;
            if (p0 + 3 < n_pairs) {
                int q = p0 >> 2;
                int4 vi = __ldg(reinterpret_cast<const int4*>(idx_i) + q);
                int4 vj = __ldg(reinterpret_cast<const int4*>(idx_j) + q);
                ii[0]=vi.x; ii[1]=vi.y; ii[2]=vi.z; ii[3]=vi.w;
                jj[0]=vj.x; jj[1]=vj.y; jj[2]=vj.z; jj[3]=vj.w;
                livemask = 0xfu;
            } else {
                livemask = 0u;
                #pragma unroll
                for (int k = 0; k < 4; k++) {
                    int p = p0 + k;
                    bool lv = (p < n_pairs);
                    livemask |= (unsigned)lv << k;
                    ii[k] = lv ? __ldg(&idx_i[p]) : 0;
                    jj[k] = lv ? __ldg(&idx_j[p]) : 0;
                }
            }

            // Batched byte-LDS lookups.
            int ca[4], cb[4];
            #pragma unroll
            for (int k = 0; k < 4; k++) ca[k] = s_cell[ii[k]];
            #pragma unroll
            for (int k = 0; k < 4; k++) cb[k] = s_cell[jj[k]];

            // Branchless adjacency mask.
            unsigned pass = 0;
            #pragma unroll
            for (int k = 0; k < 4; k++) {
                unsigned sel = (unsigned)(ca[k] - cb[k] + 43);
                unsigned long long m = (sel >= 64u) ? ADJ_HI : ADJ_LO;
                unsigned bit = (unsigned)(m >> (sel & 63u)) & 1u;
                bit &= (unsigned)(sel < 87u);
                pass |= bit << k;
            }
            pass &= livemask;

            // Warp-local compaction: ballot + popc prefix, zero atomics.
            #pragma unroll
            for (int k = 0; k < 4; k++) {
                unsigned m = __ballot_sync(0xffffffffu, (pass >> k) & 1u);
                if ((pass >> k) & 1u) {
                    int off = wcnt + __popc(m & lt);
                    obase[off] = make_int2(ii[k], jj[k]);
                }
                wcnt += __popc(m);
            }
        }

        if (lane == 0) g_cnt[c] = wcnt;
    }
}

// Kernel C: LJ on dense survivors. No smem -> high occupancy.
__global__ __launch_bounds__(256) void lj_survivors_kernel(
        const float* __restrict__ p_eps,
        const float* __restrict__ p_sig,
        const float* __restrict__ p_cut,
        int nchunks) {
    const float eps  = __ldg(p_eps);
    const float sig  = __ldg(p_sig);
    const float cut2 = __ldg(p_cut) * __ldg(p_cut);
    const float sig2 = sig * sig;

    const int lane   = threadIdx.x & 31;
    const int gwarp  = (blockIdx.x * blockDim.x + threadIdx.x) >> 5;
    const int nwarps = (gridDim.x * blockDim.x) >> 5;

    for (int c = gwarp; c < nchunks; c += nwarps) {
        int cnt = __ldg(&g_cnt[c]);
        const int2* __restrict__ sbase = g_surv + ((long long)c << 8);
        for (int r = lane; r < cnt; r += 32) {
            int2 pr = __ldg(sbase + r);
            int i = pr.x, j = pr.y;
            float4 Ri = __ldg(&g_R4[i]);
            float4 Rj = __ldg(&g_R4[j]);
            float dx = Ri.x - Rj.x;
            float dy = Ri.y - Rj.y;
            float dz = Ri.z - Rj.z;
            float r2 = fmaf(dx, dx, fmaf(dy, dy, dz * dz));
            if (r2 < cut2 && r2 > 1e-10f) {
                float inv  = __fdividef(1.0f, r2);
                float sr2  = sig2 * inv;
                float sr6  = sr2 * sr2 * sr2;
                float sr12 = sr6 * sr6;
                float e    = 2.0f * eps * (sr12 - sr6);   // 0.5*4eps folded
                float fm   = 24.0f * eps * fmaf(2.0f, sr12, -sr6) * inv;
                asm volatile("red.global.add.v4.f32 [%0], {%1, %2, %3, %4};"
                             :: "l"(&g_acc[i]),
                                "f"(e), "f"(fm * dx), "f"(fm * dy), "f"(fm * dz)
                             : "memory");
            }
        }
    }
}

// Kernel D: READ-ONLY reshape into output layout. 1 atom/thread.
__global__ void writeout_kernel(float* __restrict__ out, int n_atoms) {
    int a = blockIdx.x * blockDim.x + threadIdx.x;
    if (a < n_atoms) {
        float4 v = g_acc[a];
        out[a] = v.x;
        float* f = out + n_atoms;
        f[3 * a + 0] = v.y;
        f[3 * a + 1] = v.z;
        f[3 * a + 2] = v.w;
    }
}

extern "C" void kernel_launch(void* const* d_in, const int* in_sizes, int n_in,
                              void* d_out, int out_size) {
    const float* R     = (const float*)d_in[0];
    const float* eps   = (const float*)d_in[1];
    const float* sig   = (const float*)d_in[2];
    const float* cut   = (const float*)d_in[3];
    const int*   idx_i = (const int*)d_in[4];
    const int*   idx_j = (const int*)d_in[5];
    float*       out   = (float*)d_out;

    int n_atoms = in_sizes[0] / 3;
    int n_pairs = in_sizes[4];
    int nchunks = (n_pairs + 255) / 256;
    if (nchunks > MAX_CHUNKS) nchunks = MAX_CHUNKS;

    int smem_bytes = n_atoms;   // 1 byte per atom (200 KB)
    cudaFuncSetAttribute(filter_kernel,
                         cudaFuncAttributeMaxDynamicSharedMemorySize, smem_bytes);

    int blocks_atoms = (n_atoms + 255) / 256;

    prep_kernel<<<blocks_atoms, 256>>>(R, n_atoms, nchunks);
    filter_kernel<<<FILT_CTAS, FILT_THR, smem_bytes>>>(
        idx_i, idx_j, n_atoms, n_pairs, nchunks);
    lj_survivors_kernel<<<2048, 256>>>(eps, sig, cut, nchunks);
    writeout_kernel<<<blocks_atoms, 256>>>(out, n_atoms);
}